// round 3
// baseline (speedup 1.0000x reference)
#include <cuda_runtime.h>
#include <math.h>

#define N_NODES 50000
#define N_EDGES 800000
#define HID     128
#define N_GRAPHS 32
#define LN_EPS  1e-5f
#define SCAN_BLK ((N_NODES + 1023) / 1024)   // 49

// ---------------- scratch (device globals; no allocation allowed) ------------
__device__ float g_hcur [N_NODES * HID];
__device__ float g_hfeat[N_NODES * HID];
__device__ float g_skip [N_NODES * HID];
__device__ float g_esrc [N_NODES];
__device__ float g_edst [N_NODES];
__device__ float g_psum [N_GRAPHS * HID];
__device__ float g_pmax [N_GRAPHS * HID];
__device__ float g_cnt  [N_GRAPHS];
// CSR scratch
__device__ int   g_deg     [N_NODES];
__device__ int   g_rowstart[N_NODES + 1];
__device__ int   g_cursor  [N_NODES];
__device__ int   g_blksum  [SCAN_BLK];
__device__ int   g_blkoff  [SCAN_BLK];
__device__ int   g_csr_src [N_EDGES];

// ---------------- helpers ----------------------------------------------------
__device__ __forceinline__ void atomicMaxF(float* a, float v) {
    if (v >= 0.f) atomicMax((int*)a, __float_as_int(v));
    else          atomicMin((unsigned int*)a, __float_as_uint(v));
}

__device__ __forceinline__ void redAddV4(float* dst, float a, float b, float c, float d) {
    asm volatile("red.global.add.v4.f32 [%0], {%1,%2,%3,%4};"
                 :: "l"(dst), "f"(a), "f"(b), "f"(c), "f"(d) : "memory");
}

// =============================================================================
// GEMM: H = X @ W (+bias), optional e_src/e_dst epilogue
// BM=128, BN=128, BK=16. 256 threads as a 16x16 grid; each thread 8x8 outputs.
// =============================================================================
#define SX_STRIDE 132   // padded row stride for transposed X tile

__global__ void __launch_bounds__(256) gemm128(
    const float* __restrict__ X, const float* __restrict__ W,
    const float* __restrict__ bias,
    const float* __restrict__ a_s, const float* __restrict__ a_d,
    float* __restrict__ H, float* __restrict__ es, float* __restrict__ ed,
    int n, int computeE)
{
    __shared__ float sW[16 * 128];        // 8 KB  K-chunk of W (row-major [k][col])
    __shared__ float sX[16 * SX_STRIDE];  // 8.25 KB X tile transposed [k][row]

    const int tid  = threadIdx.x;
    const int tx   = tid & 15;            // output-col group
    const int ty   = tid >> 4;            // output-row group
    const int row0 = blockIdx.x * 128;

    float acc[8][8];
#pragma unroll
    for (int r = 0; r < 8; r++)
#pragma unroll
        for (int c = 0; c < 8; c++) acc[r][c] = 0.f;

    for (int k0 = 0; k0 < 128; k0 += 16) {
        // stage W chunk (16 x 128): 512 float4, 2 per thread
#pragma unroll
        for (int i = 0; i < 2; i++) {
            int idx = tid + i * 256;
            ((float4*)sW)[idx] = ((const float4*)(W + k0 * 128))[idx];
        }
        // stage X tile transposed: 128 rows x 16 k = 512 float4, 2 per thread
#pragma unroll
        for (int i = 0; i < 2; i++) {
            int t   = tid + i * 256;      // 0..511
            int row = t >> 2;             // 0..127
            int c4  = t & 3;              // k-group of 4
            int grow = row0 + row;
            float4 v = make_float4(0.f, 0.f, 0.f, 0.f);
            if (grow < n) v = ((const float4*)(X + grow * 128 + k0))[c4];
            sX[(c4 * 4 + 0) * SX_STRIDE + row] = v.x;
            sX[(c4 * 4 + 1) * SX_STRIDE + row] = v.y;
            sX[(c4 * 4 + 2) * SX_STRIDE + row] = v.z;
            sX[(c4 * 4 + 3) * SX_STRIDE + row] = v.w;
        }
        __syncthreads();

#pragma unroll
        for (int k = 0; k < 16; k++) {
            float4 wa = *(const float4*)(sW + k * 128 + tx * 8);
            float4 wb = *(const float4*)(sW + k * 128 + tx * 8 + 4);
            float4 xa = *(const float4*)(sX + k * SX_STRIDE + ty * 8);
            float4 xb = *(const float4*)(sX + k * SX_STRIDE + ty * 8 + 4);
            float xv[8] = {xa.x, xa.y, xa.z, xa.w, xb.x, xb.y, xb.z, xb.w};
            float wv[8] = {wa.x, wa.y, wa.z, wa.w, wb.x, wb.y, wb.z, wb.w};
#pragma unroll
            for (int r = 0; r < 8; r++)
#pragma unroll
                for (int c = 0; c < 8; c++)
                    acc[r][c] += xv[r] * wv[c];
        }
        __syncthreads();
    }

    // epilogue
    float bv[8] = {0,0,0,0,0,0,0,0};
    if (bias) {
        float4 b0 = *(const float4*)(bias + tx * 8);
        float4 b1 = *(const float4*)(bias + tx * 8 + 4);
        bv[0]=b0.x; bv[1]=b0.y; bv[2]=b0.z; bv[3]=b0.w;
        bv[4]=b1.x; bv[5]=b1.y; bv[6]=b1.z; bv[7]=b1.w;
    }
    float asv[8], adv[8];
    if (computeE) {
        float4 t0 = *(const float4*)(a_s + tx * 8);
        float4 t1 = *(const float4*)(a_s + tx * 8 + 4);
        asv[0]=t0.x; asv[1]=t0.y; asv[2]=t0.z; asv[3]=t0.w;
        asv[4]=t1.x; asv[5]=t1.y; asv[6]=t1.z; asv[7]=t1.w;
        float4 u0 = *(const float4*)(a_d + tx * 8);
        float4 u1 = *(const float4*)(a_d + tx * 8 + 4);
        adv[0]=u0.x; adv[1]=u0.y; adv[2]=u0.z; adv[3]=u0.w;
        adv[4]=u1.x; adv[5]=u1.y; adv[6]=u1.z; adv[7]=u1.w;
    }

#pragma unroll
    for (int r = 0; r < 8; r++) {
        int row = row0 + ty * 8 + r;
        bool valid = (row < n);
        float4 h0, h1;
        h0.x = acc[r][0] + bv[0]; h0.y = acc[r][1] + bv[1];
        h0.z = acc[r][2] + bv[2]; h0.w = acc[r][3] + bv[3];
        h1.x = acc[r][4] + bv[4]; h1.y = acc[r][5] + bv[5];
        h1.z = acc[r][6] + bv[6]; h1.w = acc[r][7] + bv[7];
        if (valid) {
            *(float4*)(H + (long)row * 128 + tx * 8)     = h0;
            *(float4*)(H + (long)row * 128 + tx * 8 + 4) = h1;
        }
        if (computeE) {
            float ps = h0.x*asv[0] + h0.y*asv[1] + h0.z*asv[2] + h0.w*asv[3]
                     + h1.x*asv[4] + h1.y*asv[5] + h1.z*asv[6] + h1.w*asv[7];
            float pd = h0.x*adv[0] + h0.y*adv[1] + h0.z*adv[2] + h0.w*adv[3]
                     + h1.x*adv[4] + h1.y*adv[5] + h1.z*adv[6] + h1.w*adv[7];
            // reduce across the 16 tx lanes (xor shuffles stay inside 16-lane half)
#pragma unroll
            for (int o = 8; o > 0; o >>= 1) {
                ps += __shfl_xor_sync(0xffffffff, ps, o);
                pd += __shfl_xor_sync(0xffffffff, pd, o);
            }
            if (tx == 0 && valid) { es[row] = ps; ed[row] = pd; }
        }
    }
}

// =============================================================================
// CSR construction (by destination)
// =============================================================================
__global__ void csr_zero() {
    int i = blockIdx.x * blockDim.x + threadIdx.x;
    if (i < N_NODES) g_deg[i] = 0;
}

__global__ void csr_hist(const int* __restrict__ ei) {
    int e = blockIdx.x * blockDim.x + threadIdx.x;
    if (e < N_EDGES) atomicAdd(&g_deg[__ldg(ei + N_EDGES + e)], 1);
}

__global__ void __launch_bounds__(1024) csr_scan1() {
    __shared__ int sh[1024];
    int i = blockIdx.x * 1024 + threadIdx.x;
    int v = (i < N_NODES) ? g_deg[i] : 0;
    sh[threadIdx.x] = v;
    __syncthreads();
#pragma unroll
    for (int off = 1; off < 1024; off <<= 1) {
        int t = (threadIdx.x >= off) ? sh[threadIdx.x - off] : 0;
        __syncthreads();
        sh[threadIdx.x] += t;
        __syncthreads();
    }
    if (i < N_NODES) g_rowstart[i] = sh[threadIdx.x] - v;   // exclusive
    if (threadIdx.x == 1023) g_blksum[blockIdx.x] = sh[1023];
}

__global__ void __launch_bounds__(64) csr_scan2() {
    __shared__ int sh[64];
    int t = threadIdx.x;
    int v = (t < SCAN_BLK) ? g_blksum[t] : 0;
    sh[t] = v;
    __syncthreads();
#pragma unroll
    for (int off = 1; off < 64; off <<= 1) {
        int u = (t >= off) ? sh[t - off] : 0;
        __syncthreads();
        sh[t] += u;
        __syncthreads();
    }
    if (t < SCAN_BLK) g_blkoff[t] = sh[t] - v;              // exclusive
}

__global__ void csr_scan3() {
    int i = blockIdx.x * blockDim.x + threadIdx.x;
    if (i < N_NODES) {
        int r = g_rowstart[i] + g_blkoff[i >> 10];
        g_rowstart[i] = r;
        g_cursor[i]   = r;
    }
    if (i == 0) g_rowstart[N_NODES] = N_EDGES;
}

__global__ void csr_scatter(const int* __restrict__ ei) {
    int e = blockIdx.x * blockDim.x + threadIdx.x;
    if (e >= N_EDGES) return;
    int s = __ldg(ei + e);
    int d = __ldg(ei + N_EDGES + e);
    int pos = atomicAdd(&g_cursor[d], 1);
    g_csr_src[pos] = s;
}

// =============================================================================
// Fully fused layer: softmax-gather + bias + LN + ELU + skip (+ pooling on l3)
// One warp per destination node. Zero atomics in the hot path.
// =============================================================================
__device__ __forceinline__ float edge_p(float esrc, float edst) {
    float v = esrc + edst;
    v = fmaxf(v, 0.2f * v);          // leaky_relu
    return __expf(v);                // softmax shift-invariant; logits O(1)
}

__global__ void __launch_bounds__(256) gat_layer(
    const float* __restrict__ gat_b, const float* __restrict__ ln_g,
    const float* __restrict__ ln_b, const int* __restrict__ batch, int layer)
{
    int w = (blockIdx.x * blockDim.x + threadIdx.x) >> 5;
    int lane = threadIdx.x & 31;
    if (w >= N_NODES) return;

    float ed = __ldg(g_edst + w);

    // self loop
    float p = edge_p(__ldg(g_esrc + w), ed);
    float z = p;
    float4 hv = *(const float4*)(g_hfeat + (long)w * 128 + lane * 4);
    float4 acc = make_float4(p * hv.x, p * hv.y, p * hv.z, p * hv.w);

    int i   = __ldg(g_rowstart + w);
    int end = __ldg(g_rowstart + w + 1);

    for (; i + 2 <= end; i += 2) {
        int s0 = __ldg(g_csr_src + i);
        int s1 = __ldg(g_csr_src + i + 1);
        float p0 = edge_p(__ldg(g_esrc + s0), ed);
        float p1 = edge_p(__ldg(g_esrc + s1), ed);
        float4 h0 = *(const float4*)(g_hfeat + (long)s0 * 128 + lane * 4);
        float4 h1 = *(const float4*)(g_hfeat + (long)s1 * 128 + lane * 4);
        z += p0 + p1;
        acc.x += p0 * h0.x + p1 * h1.x;
        acc.y += p0 * h0.y + p1 * h1.y;
        acc.z += p0 * h0.z + p1 * h1.z;
        acc.w += p0 * h0.w + p1 * h1.w;
    }
    if (i < end) {
        int s0 = __ldg(g_csr_src + i);
        float p0 = edge_p(__ldg(g_esrc + s0), ed);
        float4 h0 = *(const float4*)(g_hfeat + (long)s0 * 128 + lane * 4);
        z += p0;
        acc.x += p0 * h0.x; acc.y += p0 * h0.y;
        acc.z += p0 * h0.z; acc.w += p0 * h0.w;
    }

    float inv = __fdividef(1.f, z);
    float4 b4 = *(const float4*)(gat_b + lane * 4);
    float4 v;
    v.x = acc.x * inv + b4.x;
    v.y = acc.y * inv + b4.y;
    v.z = acc.z * inv + b4.z;
    v.w = acc.w * inv + b4.w;

    // layernorm over 128 features (warp reduce)
    float s  = v.x + v.y + v.z + v.w;
    float sq = v.x * v.x + v.y * v.y + v.z * v.z + v.w * v.w;
#pragma unroll
    for (int o = 16; o > 0; o >>= 1) {
        s  += __shfl_xor_sync(0xffffffff, s,  o);
        sq += __shfl_xor_sync(0xffffffff, sq, o);
    }
    float mean = s * (1.f / 128.f);
    float var  = sq * (1.f / 128.f) - mean * mean;
    float rstd = rsqrtf(var + LN_EPS);

    float4 g4 = *(const float4*)(ln_g + lane * 4);
    float4 l4 = *(const float4*)(ln_b + lane * 4);
    float y0 = (v.x - mean) * rstd * g4.x + l4.x;
    float y1 = (v.y - mean) * rstd * g4.y + l4.y;
    float y2 = (v.z - mean) * rstd * g4.z + l4.z;
    float y3 = (v.w - mean) * rstd * g4.w + l4.w;

    if (layer < 3) {   // ELU on all but last layer
        y0 = y0 > 0.f ? y0 : expm1f(y0);
        y1 = y1 > 0.f ? y1 : expm1f(y1);
        y2 = y2 > 0.f ? y2 : expm1f(y2);
        y3 = y3 > 0.f ? y3 : expm1f(y3);
    }

    const float* skp = (layer == 0) ? g_skip : g_hcur;
    float4 sk = *(const float4*)(skp + (long)w * 128 + lane * 4);
    y0 += sk.x; y1 += sk.y; y2 += sk.z; y3 += sk.w;

    *(float4*)(g_hcur + (long)w * 128 + lane * 4) = make_float4(y0, y1, y2, y3);

    if (layer == 3) {   // fused global pooling
        int g = __ldg(batch + w);
        redAddV4(g_psum + g * 128 + lane * 4, y0, y1, y2, y3);
        float* pm = g_pmax + g * 128 + lane * 4;
        atomicMaxF(pm + 0, y0);
        atomicMaxF(pm + 1, y1);
        atomicMaxF(pm + 2, y2);
        atomicMaxF(pm + 3, y3);
        if (lane == 0) atomicAdd(&g_cnt[g], 1.f);
    }
}

// ---------------- pooling init ------------------------------------------------
__global__ void pool_init() {
    int i = blockIdx.x * blockDim.x + threadIdx.x;
    if (i < N_GRAPHS * HID) {
        g_psum[i] = 0.f;
        g_pmax[i] = __int_as_float(0xFF800000);  // -inf
    }
    if (i < N_GRAPHS) g_cnt[i] = 0.f;
}

// ---------------- MLP head (one block per graph) ------------------------------
__global__ void __launch_bounds__(128) mlp_head(
    const float* __restrict__ W1, const float* __restrict__ b1,
    const float* __restrict__ W2, const float* __restrict__ b2,
    const float* __restrict__ W3, const float* __restrict__ b3,
    float* __restrict__ out)
{
    __shared__ float gv[256];
    __shared__ float h1[128];
    __shared__ float h2[64];
    int g = blockIdx.x, t = threadIdx.x;

    float cnt = fmaxf(g_cnt[g], 1.f);
    gv[t]       = g_psum[g * 128 + t] / cnt;  // mean half
    gv[128 + t] = g_pmax[g * 128 + t];        // max half
    __syncthreads();

    float a1 = b1[t];
#pragma unroll 8
    for (int k = 0; k < 256; k++) a1 += gv[k] * W1[k * 128 + t];
    h1[t] = fmaxf(a1, 0.f);
    __syncthreads();

    if (t < 64) {
        float a2 = b2[t];
#pragma unroll 8
        for (int k = 0; k < 128; k++) a2 += h1[k] * W2[k * 64 + t];
        h2[t] = fmaxf(a2, 0.f);
    }
    __syncthreads();

    if (t < 4) {
        float a3 = b3[t];
#pragma unroll
        for (int k = 0; k < 64; k++) a3 += h2[k] * W3[k * 4 + t];
        out[g * 4 + t] = a3;
    }
}

// ---------------- launch ------------------------------------------------------
extern "C" void kernel_launch(void* const* d_in, const int* in_sizes, int n_in,
                              void* d_out, int out_size)
{
    const float* x      = (const float*)d_in[0];
    const int*   ei     = (const int*)  d_in[1];
    const int*   batch  = (const int*)  d_in[2];
    const float* Ws     = (const float*)d_in[3];
    const float* a_src  = (const float*)d_in[4];
    const float* a_dst  = (const float*)d_in[5];
    const float* gat_b  = (const float*)d_in[6];
    const float* ln_g   = (const float*)d_in[7];
    const float* ln_b   = (const float*)d_in[8];
    const float* skip_W = (const float*)d_in[9];
    const float* skip_b = (const float*)d_in[10];
    const float* W1 = (const float*)d_in[11];
    const float* b1 = (const float*)d_in[12];
    const float* W2 = (const float*)d_in[13];
    const float* b2 = (const float*)d_in[14];
    const float* W3 = (const float*)d_in[15];
    const float* b3 = (const float*)d_in[16];

    float *hcur, *hfeat, *skip, *esrc, *edst;
    cudaGetSymbolAddress((void**)&hcur,  g_hcur);
    cudaGetSymbolAddress((void**)&hfeat, g_hfeat);
    cudaGetSymbolAddress((void**)&skip,  g_skip);
    cudaGetSymbolAddress((void**)&esrc,  g_esrc);
    cudaGetSymbolAddress((void**)&edst,  g_edst);

    const int gemm_blocks = (N_NODES + 127) / 128;
    const int node_blocks = (N_NODES * 32 + 255) / 256;   // warp per node
    const int edge_blocks = (N_EDGES + 255) / 256;
    const int nn_blocks   = (N_NODES + 255) / 256;

    // CSR build (dst-major)
    csr_zero   <<<nn_blocks, 256>>>();
    csr_hist   <<<edge_blocks, 256>>>(ei);
    csr_scan1  <<<SCAN_BLK, 1024>>>();
    csr_scan2  <<<1, 64>>>();
    csr_scan3  <<<nn_blocks, 256>>>();
    csr_scatter<<<edge_blocks, 256>>>(ei);

    pool_init<<<(N_GRAPHS * HID + 255) / 256, 256>>>();

    // skip projection
    gemm128<<<gemm_blocks, 256>>>(x, skip_W, skip_b, nullptr, nullptr,
                                  skip, nullptr, nullptr, N_NODES, 0);

    for (int l = 0; l < 4; l++) {
        const float* in = (l == 0) ? x : hcur;
        gemm128<<<gemm_blocks, 256>>>(in, Ws + l * 128 * 128, nullptr,
                                      a_src + l * 128, a_dst + l * 128,
                                      hfeat, esrc, edst, N_NODES, 1);
        gat_layer<<<node_blocks, 256>>>(gat_b + l * 128, ln_g + l * 128,
                                        ln_b + l * 128, batch, l);
    }

    mlp_head<<<N_GRAPHS, 128>>>(W1, b1, W2, b2, W3, b3, (float*)d_out);
}

// round 4
// speedup vs baseline: 1.0376x; 1.0376x over previous
#include <cuda_runtime.h>
#include <math.h>

#define N_NODES 50000
#define N_EDGES 800000
#define HID     128
#define N_GRAPHS 32
#define LN_EPS  1e-5f
#define SCAN_BLK ((N_NODES + 1023) / 1024)   // 49

// ---------------- scratch (device globals; no allocation allowed) ------------
__device__ float g_hcur [N_NODES * HID];
__device__ float g_hfeat[N_NODES * HID];
__device__ float g_skip [N_NODES * HID];
__device__ float g_esrc [N_NODES];
__device__ float g_edst [N_NODES];
__device__ float g_psum [N_GRAPHS * HID];
__device__ float g_pmax [N_GRAPHS * HID];
__device__ float g_cnt  [N_GRAPHS];
// CSR scratch
__device__ int   g_deg     [N_NODES];
__device__ int   g_rowstart[N_NODES + 1];
__device__ int   g_cursor  [N_NODES];
__device__ int   g_blksum  [SCAN_BLK];
__device__ int   g_blkoff  [SCAN_BLK];
__device__ int   g_csr_src [N_EDGES];

// ---------------- helpers ----------------------------------------------------
__device__ __forceinline__ void atomicMaxF(float* a, float v) {
    if (v >= 0.f) atomicMax((int*)a, __float_as_int(v));
    else          atomicMin((unsigned int*)a, __float_as_uint(v));
}

__device__ __forceinline__ void redAddV4(float* dst, float a, float b, float c, float d) {
    asm volatile("red.global.add.v4.f32 [%0], {%1,%2,%3,%4};"
                 :: "l"(dst), "f"(a), "f"(b), "f"(c), "f"(d) : "memory");
}

// packed fp32x2 (sm_103a): 2 full-precision FMAs per fma-pipe slot
__device__ __forceinline__ unsigned long long pk2(float a, float b) {
    unsigned long long r;
    asm("mov.b64 %0, {%1, %2};" : "=l"(r) : "f"(a), "f"(b));
    return r;
}
__device__ __forceinline__ void fma2(unsigned long long& d,
                                     unsigned long long a, unsigned long long b) {
    asm("fma.rn.f32x2 %0, %1, %2, %0;" : "+l"(d) : "l"(a), "l"(b));
}
__device__ __forceinline__ float2 upk2(unsigned long long v) {
    float2 f;
    asm("mov.b64 {%0, %1}, %2;" : "=f"(f.x), "=f"(f.y) : "l"(v));
    return f;
}

// =============================================================================
// GEMM: H = X @ W (+bias), optional e_src/e_dst epilogue
// BM=64, BN=128, BK=32. 256 threads. Each thread: 8 rows x 4 cols (f32x2 core).
// =============================================================================
__global__ void __launch_bounds__(256) gemm128(
    const float* __restrict__ X, const float* __restrict__ W,
    const float* __restrict__ bias,
    const float* __restrict__ a_s, const float* __restrict__ a_d,
    float* __restrict__ H, float* __restrict__ es, float* __restrict__ ed,
    int n, int computeE)
{
    __shared__ float sW [32 * 128];   // 16 KB  (K-chunk of W, row-major)
    __shared__ float sXT[32 * 64];    //  8 KB  (X tile, transposed: [k][row])

    const int tid  = threadIdx.x;
    const int warp = tid >> 5;
    const int lane = tid & 31;
    const int row0 = blockIdx.x * 64;

    unsigned long long acc01[8], acc23[8];
#pragma unroll
    for (int r = 0; r < 8; r++) { acc01[r] = 0ull; acc23[r] = 0ull; }

    for (int k0 = 0; k0 < 128; k0 += 32) {
        // stage W chunk (32 x 128)
#pragma unroll
        for (int i = 0; i < 4; i++) {
            int idx = tid + i * 256;                     // float4 idx 0..1023
            ((float4*)sW)[idx] = ((const float4*)(W + k0 * 128))[idx];
        }
        // stage X tile transposed (rows 64 x k 32)
#pragma unroll
        for (int i = 0; i < 2; i++) {
            int t   = tid + i * 256;                     // 0..511
            int row = t & 63;
            int c4  = t >> 6;                            // k-group (0..7)
            int grow = row0 + row;
            float4 v = make_float4(0.f, 0.f, 0.f, 0.f);
            if (grow < n) v = ((const float4*)(X + grow * 128 + k0))[c4];
            sXT[(c4 * 4 + 0) * 64 + row] = v.x;
            sXT[(c4 * 4 + 1) * 64 + row] = v.y;
            sXT[(c4 * 4 + 2) * 64 + row] = v.z;
            sXT[(c4 * 4 + 3) * 64 + row] = v.w;
        }
        __syncthreads();

#pragma unroll
        for (int k = 0; k < 32; k++) {
            float4 w4 = *(const float4*)(sW  + k * 128 + lane * 4);
            float4 xa = *(const float4*)(sXT + k * 64  + warp * 8);
            float4 xb = *(const float4*)(sXT + k * 64  + warp * 8 + 4);
            unsigned long long w01 = pk2(w4.x, w4.y);
            unsigned long long w23 = pk2(w4.z, w4.w);
            float xv[8] = {xa.x, xa.y, xa.z, xa.w, xb.x, xb.y, xb.z, xb.w};
#pragma unroll
            for (int r = 0; r < 8; r++) {
                unsigned long long xx = pk2(xv[r], xv[r]);
                fma2(acc01[r], xx, w01);
                fma2(acc23[r], xx, w23);
            }
        }
        __syncthreads();
    }

    float4 bv = make_float4(0.f, 0.f, 0.f, 0.f);
    if (bias) bv = *(const float4*)(bias + lane * 4);
    float4 as4 = make_float4(0.f, 0.f, 0.f, 0.f);
    float4 ad4 = make_float4(0.f, 0.f, 0.f, 0.f);
    if (computeE) {
        as4 = *(const float4*)(a_s + lane * 4);
        ad4 = *(const float4*)(a_d + lane * 4);
    }

#pragma unroll
    for (int r = 0; r < 8; r++) {
        int row = row0 + warp * 8 + r;
        if (row < n) {
            float2 p01 = upk2(acc01[r]);
            float2 p23 = upk2(acc23[r]);
            float4 h = make_float4(p01.x + bv.x, p01.y + bv.y,
                                   p23.x + bv.z, p23.y + bv.w);
            *(float4*)(H + (long)row * 128 + lane * 4) = h;
            if (computeE) {
                float ps = h.x * as4.x + h.y * as4.y + h.z * as4.z + h.w * as4.w;
                float pd = h.x * ad4.x + h.y * ad4.y + h.z * ad4.z + h.w * ad4.w;
#pragma unroll
                for (int o = 16; o > 0; o >>= 1) {
                    ps += __shfl_xor_sync(0xffffffff, ps, o);
                    pd += __shfl_xor_sync(0xffffffff, pd, o);
                }
                if (lane == 0) { es[row] = ps; ed[row] = pd; }
            }
        }
    }
}

// =============================================================================
// CSR construction (by destination)  [csr_zero also inits pooling buffers]
// =============================================================================
__global__ void csr_zero() {
    int i = blockIdx.x * blockDim.x + threadIdx.x;
    if (i < N_NODES) g_deg[i] = 0;
    if (i < N_GRAPHS * HID) {
        g_psum[i] = 0.f;
        g_pmax[i] = __int_as_float(0xFF800000);  // -inf
    }
    if (i < N_GRAPHS) g_cnt[i] = 0.f;
}

__global__ void csr_hist(const int* __restrict__ ei) {
    int e = blockIdx.x * blockDim.x + threadIdx.x;
    if (e < N_EDGES) atomicAdd(&g_deg[__ldg(ei + N_EDGES + e)], 1);
}

__global__ void __launch_bounds__(1024) csr_scan1() {
    __shared__ int sh[1024];
    int i = blockIdx.x * 1024 + threadIdx.x;
    int v = (i < N_NODES) ? g_deg[i] : 0;
    sh[threadIdx.x] = v;
    __syncthreads();
#pragma unroll
    for (int off = 1; off < 1024; off <<= 1) {
        int t = (threadIdx.x >= off) ? sh[threadIdx.x - off] : 0;
        __syncthreads();
        sh[threadIdx.x] += t;
        __syncthreads();
    }
    if (i < N_NODES) g_rowstart[i] = sh[threadIdx.x] - v;   // exclusive
    if (threadIdx.x == 1023) g_blksum[blockIdx.x] = sh[1023];
}

__global__ void __launch_bounds__(64) csr_scan2() {
    __shared__ int sh[64];
    int t = threadIdx.x;
    int v = (t < SCAN_BLK) ? g_blksum[t] : 0;
    sh[t] = v;
    __syncthreads();
#pragma unroll
    for (int off = 1; off < 64; off <<= 1) {
        int u = (t >= off) ? sh[t - off] : 0;
        __syncthreads();
        sh[t] += u;
        __syncthreads();
    }
    if (t < SCAN_BLK) g_blkoff[t] = sh[t] - v;              // exclusive
}

__global__ void csr_scan3() {
    int i = blockIdx.x * blockDim.x + threadIdx.x;
    if (i < N_NODES) {
        int r = g_rowstart[i] + g_blkoff[i >> 10];
        g_rowstart[i] = r;
        g_cursor[i]   = r;
    }
    if (i == 0) g_rowstart[N_NODES] = N_EDGES;
}

__global__ void csr_scatter(const int* __restrict__ ei) {
    int e = blockIdx.x * blockDim.x + threadIdx.x;
    if (e >= N_EDGES) return;
    int s = __ldg(ei + e);
    int d = __ldg(ei + N_EDGES + e);
    int pos = atomicAdd(&g_cursor[d], 1);
    g_csr_src[pos] = s;
}

// =============================================================================
// Fully fused layer: softmax-gather + bias + LN + ELU + skip (+ pooling on l3)
// One warp per destination node. Zero atomics in the hot path.
// =============================================================================
__device__ __forceinline__ float edge_p(float esrc, float edst) {
    float v = esrc + edst;
    v = fmaxf(v, 0.2f * v);          // leaky_relu
    return __expf(v);                // softmax shift-invariant; logits O(1)
}

__global__ void __launch_bounds__(256) gat_layer(
    const float* __restrict__ gat_b, const float* __restrict__ ln_g,
    const float* __restrict__ ln_b, const int* __restrict__ batch, int layer)
{
    int w = (blockIdx.x * blockDim.x + threadIdx.x) >> 5;
    int lane = threadIdx.x & 31;
    if (w >= N_NODES) return;

    float ed = __ldg(g_edst + w);

    // self loop
    float p = edge_p(__ldg(g_esrc + w), ed);
    float z = p;
    float4 hv = *(const float4*)(g_hfeat + (long)w * 128 + lane * 4);
    float4 acc = make_float4(p * hv.x, p * hv.y, p * hv.z, p * hv.w);

    int i   = __ldg(g_rowstart + w);
    int end = __ldg(g_rowstart + w + 1);

    for (; i + 2 <= end; i += 2) {
        int s0 = __ldg(g_csr_src + i);
        int s1 = __ldg(g_csr_src + i + 1);
        float p0 = edge_p(__ldg(g_esrc + s0), ed);
        float p1 = edge_p(__ldg(g_esrc + s1), ed);
        float4 h0 = *(const float4*)(g_hfeat + (long)s0 * 128 + lane * 4);
        float4 h1 = *(const float4*)(g_hfeat + (long)s1 * 128 + lane * 4);
        z += p0 + p1;
        acc.x += p0 * h0.x + p1 * h1.x;
        acc.y += p0 * h0.y + p1 * h1.y;
        acc.z += p0 * h0.z + p1 * h1.z;
        acc.w += p0 * h0.w + p1 * h1.w;
    }
    if (i < end) {
        int s0 = __ldg(g_csr_src + i);
        float p0 = edge_p(__ldg(g_esrc + s0), ed);
        float4 h0 = *(const float4*)(g_hfeat + (long)s0 * 128 + lane * 4);
        z += p0;
        acc.x += p0 * h0.x; acc.y += p0 * h0.y;
        acc.z += p0 * h0.z; acc.w += p0 * h0.w;
    }

    float inv = __fdividef(1.f, z);
    float4 b4 = *(const float4*)(gat_b + lane * 4);
    float4 v;
    v.x = acc.x * inv + b4.x;
    v.y = acc.y * inv + b4.y;
    v.z = acc.z * inv + b4.z;
    v.w = acc.w * inv + b4.w;

    // layernorm over 128 features (warp reduce)
    float s  = v.x + v.y + v.z + v.w;
    float sq = v.x * v.x + v.y * v.y + v.z * v.z + v.w * v.w;
#pragma unroll
    for (int o = 16; o > 0; o >>= 1) {
        s  += __shfl_xor_sync(0xffffffff, s,  o);
        sq += __shfl_xor_sync(0xffffffff, sq, o);
    }
    float mean = s * (1.f / 128.f);
    float var  = sq * (1.f / 128.f) - mean * mean;
    float rstd = rsqrtf(var + LN_EPS);

    float4 g4 = *(const float4*)(ln_g + lane * 4);
    float4 l4 = *(const float4*)(ln_b + lane * 4);
    float y0 = (v.x - mean) * rstd * g4.x + l4.x;
    float y1 = (v.y - mean) * rstd * g4.y + l4.y;
    float y2 = (v.z - mean) * rstd * g4.z + l4.z;
    float y3 = (v.w - mean) * rstd * g4.w + l4.w;

    if (layer < 3) {   // ELU on all but last layer
        y0 = y0 > 0.f ? y0 : expm1f(y0);
        y1 = y1 > 0.f ? y1 : expm1f(y1);
        y2 = y2 > 0.f ? y2 : expm1f(y2);
        y3 = y3 > 0.f ? y3 : expm1f(y3);
    }

    const float* skp = (layer == 0) ? g_skip : g_hcur;
    float4 sk = *(const float4*)(skp + (long)w * 128 + lane * 4);
    y0 += sk.x; y1 += sk.y; y2 += sk.z; y3 += sk.w;

    *(float4*)(g_hcur + (long)w * 128 + lane * 4) = make_float4(y0, y1, y2, y3);

    if (layer == 3) {   // fused global pooling
        int g = __ldg(batch + w);
        redAddV4(g_psum + g * 128 + lane * 4, y0, y1, y2, y3);
        float* pm = g_pmax + g * 128 + lane * 4;
        atomicMaxF(pm + 0, y0);
        atomicMaxF(pm + 1, y1);
        atomicMaxF(pm + 2, y2);
        atomicMaxF(pm + 3, y3);
        if (lane == 0) atomicAdd(&g_cnt[g], 1.f);
    }
}

// ---------------- MLP head (one block per graph) ------------------------------
__global__ void __launch_bounds__(128) mlp_head(
    const float* __restrict__ W1, const float* __restrict__ b1,
    const float* __restrict__ W2, const float* __restrict__ b2,
    const float* __restrict__ W3, const float* __restrict__ b3,
    float* __restrict__ out)
{
    __shared__ float gv[256];
    __shared__ float h1[128];
    __shared__ float h2[64];
    int g = blockIdx.x, t = threadIdx.x;

    float cnt = fmaxf(g_cnt[g], 1.f);
    gv[t]       = g_psum[g * 128 + t] / cnt;  // mean half
    gv[128 + t] = g_pmax[g * 128 + t];        // max half
    __syncthreads();

    float a1 = b1[t];
#pragma unroll 8
    for (int k = 0; k < 256; k++) a1 += gv[k] * W1[k * 128 + t];
    h1[t] = fmaxf(a1, 0.f);
    __syncthreads();

    if (t < 64) {
        float a2 = b2[t];
#pragma unroll 8
        for (int k = 0; k < 128; k++) a2 += h1[k] * W2[k * 64 + t];
        h2[t] = fmaxf(a2, 0.f);
    }
    __syncthreads();

    if (t < 4) {
        float a3 = b3[t];
#pragma unroll
        for (int k = 0; k < 64; k++) a3 += h2[k] * W3[k * 4 + t];
        out[g * 4 + t] = a3;
    }
}

// ---------------- launch ------------------------------------------------------
extern "C" void kernel_launch(void* const* d_in, const int* in_sizes, int n_in,
                              void* d_out, int out_size)
{
    const float* x      = (const float*)d_in[0];
    const int*   ei     = (const int*)  d_in[1];
    const int*   batch  = (const int*)  d_in[2];
    const float* Ws     = (const float*)d_in[3];
    const float* a_src  = (const float*)d_in[4];
    const float* a_dst  = (const float*)d_in[5];
    const float* gat_b  = (const float*)d_in[6];
    const float* ln_g   = (const float*)d_in[7];
    const float* ln_b   = (const float*)d_in[8];
    const float* skip_W = (const float*)d_in[9];
    const float* skip_b = (const float*)d_in[10];
    const float* W1 = (const float*)d_in[11];
    const float* b1 = (const float*)d_in[12];
    const float* W2 = (const float*)d_in[13];
    const float* b2 = (const float*)d_in[14];
    const float* W3 = (const float*)d_in[15];
    const float* b3 = (const float*)d_in[16];

    float *hcur, *hfeat, *skip, *esrc, *edst;
    cudaGetSymbolAddress((void**)&hcur,  g_hcur);
    cudaGetSymbolAddress((void**)&hfeat, g_hfeat);
    cudaGetSymbolAddress((void**)&skip,  g_skip);
    cudaGetSymbolAddress((void**)&esrc,  g_esrc);
    cudaGetSymbolAddress((void**)&edst,  g_edst);

    const int gemm_blocks = (N_NODES + 63) / 64;
    const int node_blocks = (N_NODES * 32 + 255) / 256;   // warp per node
    const int edge_blocks = (N_EDGES + 255) / 256;
    const int nn_blocks   = (N_NODES + 255) / 256;

    // CSR build (dst-major) + pooling init
    csr_zero   <<<nn_blocks, 256>>>();
    csr_hist   <<<edge_blocks, 256>>>(ei);
    csr_scan1  <<<SCAN_BLK, 1024>>>();
    csr_scan2  <<<1, 64>>>();
    csr_scan3  <<<nn_blocks, 256>>>();
    csr_scatter<<<edge_blocks, 256>>>(ei);

    // skip projection
    gemm128<<<gemm_blocks, 256>>>(x, skip_W, skip_b, nullptr, nullptr,
                                  skip, nullptr, nullptr, N_NODES, 0);

    for (int l = 0; l < 4; l++) {
        const float* in = (l == 0) ? x : hcur;
        gemm128<<<gemm_blocks, 256>>>(in, Ws + l * 128 * 128, nullptr,
                                      a_src + l * 128, a_dst + l * 128,
                                      hfeat, esrc, edst, N_NODES, 1);
        gat_layer<<<node_blocks, 256>>>(gat_b + l * 128, ln_g + l * 128,
                                        ln_b + l * 128, batch, l);
    }

    mlp_head<<<N_GRAPHS, 128>>>(W1, b1, W2, b2, W3, b3, (float*)d_out);
}

// round 5
// speedup vs baseline: 1.0384x; 1.0007x over previous
#include <cuda_runtime.h>
#include <math.h>

#define N_NODES 50000
#define N_EDGES 800000
#define HID     128
#define N_GRAPHS 32
#define LN_EPS  1e-5f
#define SCAN_BLK ((N_NODES + 1023) / 1024)   // 49

// ---------------- scratch (device globals; no allocation allowed) ------------
__device__ float g_hcur [N_NODES * HID];
__device__ float g_hfeat[N_NODES * HID];
__device__ float g_skip [N_NODES * HID];
__device__ float g_esrc [N_NODES];
__device__ float g_edst [N_NODES];
__device__ float g_psum [N_GRAPHS * HID];
__device__ float g_pmax [N_GRAPHS * HID];
__device__ float g_cnt  [N_GRAPHS];
// CSR scratch
__device__ int   g_deg     [N_NODES];
__device__ int   g_rowstart[N_NODES + 1];
__device__ int   g_cursor  [N_NODES];
__device__ int   g_blksum  [SCAN_BLK];
__device__ int   g_blkoff  [SCAN_BLK];
__device__ int   g_csr_src [N_EDGES];

// ---------------- helpers ----------------------------------------------------
__device__ __forceinline__ void atomicMaxF(float* a, float v) {
    if (v >= 0.f) atomicMax((int*)a, __float_as_int(v));
    else          atomicMin((unsigned int*)a, __float_as_uint(v));
}

__device__ __forceinline__ void redAddV4(float* dst, float a, float b, float c, float d) {
    asm volatile("red.global.add.v4.f32 [%0], {%1,%2,%3,%4};"
                 :: "l"(dst), "f"(a), "f"(b), "f"(c), "f"(d) : "memory");
}

// packed fp32x2 (sm_103a): 2 full-precision FMAs per fma-pipe slot
__device__ __forceinline__ unsigned long long pk2(float a, float b) {
    unsigned long long r;
    asm("mov.b64 %0, {%1, %2};" : "=l"(r) : "f"(a), "f"(b));
    return r;
}
__device__ __forceinline__ void fma2(unsigned long long& d,
                                     unsigned long long a, unsigned long long b) {
    asm("fma.rn.f32x2 %0, %1, %2, %0;" : "+l"(d) : "l"(a), "l"(b));
}
__device__ __forceinline__ float2 upk2(unsigned long long v) {
    float2 f;
    asm("mov.b64 {%0, %1}, %2;" : "=f"(f.x), "=f"(f.y) : "l"(v));
    return f;
}

// =============================================================================
// GEMM: H = X @ W (+bias), optional e_src/e_dst epilogue
// BM=64, BN=128, BK=32. 256 threads. Each thread: 8 rows x 4 cols (f32x2 core).
// =============================================================================
__global__ void __launch_bounds__(256) gemm128(
    const float* __restrict__ X, const float* __restrict__ W,
    const float* __restrict__ a_s, const float* __restrict__ a_d,
    float* __restrict__ H, float* __restrict__ es, float* __restrict__ ed,
    int n)
{
    __shared__ float sW [32 * 128];   // 16 KB  (K-chunk of W, row-major)
    __shared__ float sXT[32 * 64];    //  8 KB  (X tile, transposed: [k][row])

    const int tid  = threadIdx.x;
    const int warp = tid >> 5;
    const int lane = tid & 31;
    const int row0 = blockIdx.x * 64;

    unsigned long long acc01[8], acc23[8];
#pragma unroll
    for (int r = 0; r < 8; r++) { acc01[r] = 0ull; acc23[r] = 0ull; }

    for (int k0 = 0; k0 < 128; k0 += 32) {
#pragma unroll
        for (int i = 0; i < 4; i++) {
            int idx = tid + i * 256;
            ((float4*)sW)[idx] = ((const float4*)(W + k0 * 128))[idx];
        }
#pragma unroll
        for (int i = 0; i < 2; i++) {
            int t   = tid + i * 256;
            int row = t & 63;
            int c4  = t >> 6;
            int grow = row0 + row;
            float4 v = make_float4(0.f, 0.f, 0.f, 0.f);
            if (grow < n) v = ((const float4*)(X + grow * 128 + k0))[c4];
            sXT[(c4 * 4 + 0) * 64 + row] = v.x;
            sXT[(c4 * 4 + 1) * 64 + row] = v.y;
            sXT[(c4 * 4 + 2) * 64 + row] = v.z;
            sXT[(c4 * 4 + 3) * 64 + row] = v.w;
        }
        __syncthreads();

#pragma unroll
        for (int k = 0; k < 32; k++) {
            float4 w4 = *(const float4*)(sW  + k * 128 + lane * 4);
            float4 xa = *(const float4*)(sXT + k * 64  + warp * 8);
            float4 xb = *(const float4*)(sXT + k * 64  + warp * 8 + 4);
            unsigned long long w01 = pk2(w4.x, w4.y);
            unsigned long long w23 = pk2(w4.z, w4.w);
            float xv[8] = {xa.x, xa.y, xa.z, xa.w, xb.x, xb.y, xb.z, xb.w};
#pragma unroll
            for (int r = 0; r < 8; r++) {
                unsigned long long xx = pk2(xv[r], xv[r]);
                fma2(acc01[r], xx, w01);
                fma2(acc23[r], xx, w23);
            }
        }
        __syncthreads();
    }

    float4 as4 = *(const float4*)(a_s + lane * 4);
    float4 ad4 = *(const float4*)(a_d + lane * 4);

#pragma unroll
    for (int r = 0; r < 8; r++) {
        int row = row0 + warp * 8 + r;
        if (row < n) {
            float2 p01 = upk2(acc01[r]);
            float2 p23 = upk2(acc23[r]);
            float4 h = make_float4(p01.x, p01.y, p23.x, p23.y);
            *(float4*)(H + (long)row * 128 + lane * 4) = h;
            float ps = h.x * as4.x + h.y * as4.y + h.z * as4.z + h.w * as4.w;
            float pd = h.x * ad4.x + h.y * ad4.y + h.z * ad4.z + h.w * ad4.w;
#pragma unroll
            for (int o = 16; o > 0; o >>= 1) {
                ps += __shfl_xor_sync(0xffffffff, ps, o);
                pd += __shfl_xor_sync(0xffffffff, pd, o);
            }
            if (lane == 0) { es[row] = ps; ed[row] = pd; }
        }
    }
}

// =============================================================================
// Dual GEMM for layer 0: H = X@W0 (+ attention epilogue) AND skip = X@Wskip+b.
// Shares the staged X tile between both weight matrices.
// =============================================================================
__global__ void __launch_bounds__(256) gemm128_dual(
    const float* __restrict__ X,
    const float* __restrict__ W0,
    const float* __restrict__ Wsk, const float* __restrict__ bsk,
    const float* __restrict__ a_s, const float* __restrict__ a_d,
    float* __restrict__ H, float* __restrict__ SK,
    float* __restrict__ es, float* __restrict__ ed,
    int n)
{
    __shared__ float sW [32 * 128];   // W0 chunk
    __shared__ float sW2[32 * 128];   // Wsk chunk
    __shared__ float sXT[32 * 64];

    const int tid  = threadIdx.x;
    const int warp = tid >> 5;
    const int lane = tid & 31;
    const int row0 = blockIdx.x * 64;

    unsigned long long a01[8], a23[8], b01[8], b23[8];
#pragma unroll
    for (int r = 0; r < 8; r++) { a01[r]=0ull; a23[r]=0ull; b01[r]=0ull; b23[r]=0ull; }

    for (int k0 = 0; k0 < 128; k0 += 32) {
#pragma unroll
        for (int i = 0; i < 4; i++) {
            int idx = tid + i * 256;
            ((float4*)sW )[idx] = ((const float4*)(W0  + k0 * 128))[idx];
            ((float4*)sW2)[idx] = ((const float4*)(Wsk + k0 * 128))[idx];
        }
#pragma unroll
        for (int i = 0; i < 2; i++) {
            int t   = tid + i * 256;
            int row = t & 63;
            int c4  = t >> 6;
            int grow = row0 + row;
            float4 v = make_float4(0.f, 0.f, 0.f, 0.f);
            if (grow < n) v = ((const float4*)(X + grow * 128 + k0))[c4];
            sXT[(c4 * 4 + 0) * 64 + row] = v.x;
            sXT[(c4 * 4 + 1) * 64 + row] = v.y;
            sXT[(c4 * 4 + 2) * 64 + row] = v.z;
            sXT[(c4 * 4 + 3) * 64 + row] = v.w;
        }
        __syncthreads();

#pragma unroll
        for (int k = 0; k < 32; k++) {
            float4 w4 = *(const float4*)(sW  + k * 128 + lane * 4);
            float4 u4 = *(const float4*)(sW2 + k * 128 + lane * 4);
            float4 xa = *(const float4*)(sXT + k * 64  + warp * 8);
            float4 xb = *(const float4*)(sXT + k * 64  + warp * 8 + 4);
            unsigned long long w01 = pk2(w4.x, w4.y);
            unsigned long long w23 = pk2(w4.z, w4.w);
            unsigned long long u01 = pk2(u4.x, u4.y);
            unsigned long long u23 = pk2(u4.z, u4.w);
            float xv[8] = {xa.x, xa.y, xa.z, xa.w, xb.x, xb.y, xb.z, xb.w};
#pragma unroll
            for (int r = 0; r < 8; r++) {
                unsigned long long xx = pk2(xv[r], xv[r]);
                fma2(a01[r], xx, w01);
                fma2(a23[r], xx, w23);
                fma2(b01[r], xx, u01);
                fma2(b23[r], xx, u23);
            }
        }
        __syncthreads();
    }

    float4 as4 = *(const float4*)(a_s + lane * 4);
    float4 ad4 = *(const float4*)(a_d + lane * 4);
    float4 bk4 = *(const float4*)(bsk + lane * 4);

#pragma unroll
    for (int r = 0; r < 8; r++) {
        int row = row0 + warp * 8 + r;
        if (row < n) {
            float2 p01 = upk2(a01[r]);
            float2 p23 = upk2(a23[r]);
            float4 h = make_float4(p01.x, p01.y, p23.x, p23.y);
            *(float4*)(H + (long)row * 128 + lane * 4) = h;

            float2 q01 = upk2(b01[r]);
            float2 q23 = upk2(b23[r]);
            float4 sk = make_float4(q01.x + bk4.x, q01.y + bk4.y,
                                    q23.x + bk4.z, q23.y + bk4.w);
            *(float4*)(SK + (long)row * 128 + lane * 4) = sk;

            float ps = h.x * as4.x + h.y * as4.y + h.z * as4.z + h.w * as4.w;
            float pd = h.x * ad4.x + h.y * ad4.y + h.z * ad4.z + h.w * ad4.w;
#pragma unroll
            for (int o = 16; o > 0; o >>= 1) {
                ps += __shfl_xor_sync(0xffffffff, ps, o);
                pd += __shfl_xor_sync(0xffffffff, pd, o);
            }
            if (lane == 0) { es[row] = ps; ed[row] = pd; }
        }
    }
}

// =============================================================================
// CSR construction (by destination)  [csr_zero also inits pooling buffers]
// =============================================================================
__global__ void csr_zero() {
    int i = blockIdx.x * blockDim.x + threadIdx.x;
    if (i < N_NODES) g_deg[i] = 0;
    if (i < N_GRAPHS * HID) {
        g_psum[i] = 0.f;
        g_pmax[i] = __int_as_float(0xFF800000);  // -inf
    }
    if (i < N_GRAPHS) g_cnt[i] = 0.f;
}

__global__ void csr_hist(const int* __restrict__ ei) {
    int e = blockIdx.x * blockDim.x + threadIdx.x;
    if (e < N_EDGES) atomicAdd(&g_deg[__ldg(ei + N_EDGES + e)], 1);
}

__global__ void __launch_bounds__(1024) csr_scan1() {
    __shared__ int sh[1024];
    int i = blockIdx.x * 1024 + threadIdx.x;
    int v = (i < N_NODES) ? g_deg[i] : 0;
    sh[threadIdx.x] = v;
    __syncthreads();
#pragma unroll
    for (int off = 1; off < 1024; off <<= 1) {
        int t = (threadIdx.x >= off) ? sh[threadIdx.x - off] : 0;
        __syncthreads();
        sh[threadIdx.x] += t;
        __syncthreads();
    }
    if (i < N_NODES) g_rowstart[i] = sh[threadIdx.x] - v;   // exclusive
    if (threadIdx.x == 1023) g_blksum[blockIdx.x] = sh[1023];
}

__global__ void __launch_bounds__(64) csr_scan2() {
    __shared__ int sh[64];
    int t = threadIdx.x;
    int v = (t < SCAN_BLK) ? g_blksum[t] : 0;
    sh[t] = v;
    __syncthreads();
#pragma unroll
    for (int off = 1; off < 64; off <<= 1) {
        int u = (t >= off) ? sh[t - off] : 0;
        __syncthreads();
        sh[t] += u;
        __syncthreads();
    }
    if (t < SCAN_BLK) g_blkoff[t] = sh[t] - v;              // exclusive
}

__global__ void csr_scan3() {
    int i = blockIdx.x * blockDim.x + threadIdx.x;
    if (i < N_NODES) {
        int r = g_rowstart[i] + g_blkoff[i >> 10];
        g_rowstart[i] = r;
        g_cursor[i]   = r;
    }
    if (i == 0) g_rowstart[N_NODES] = N_EDGES;
}

__global__ void csr_scatter(const int* __restrict__ ei) {
    int e = blockIdx.x * blockDim.x + threadIdx.x;
    if (e >= N_EDGES) return;
    int s = __ldg(ei + e);
    int d = __ldg(ei + N_EDGES + e);
    int pos = atomicAdd(&g_cursor[d], 1);
    g_csr_src[pos] = s;
}

// =============================================================================
// Fully fused layer: softmax-gather + bias + LN + ELU + skip (+ pooling on l3)
// One warp per destination node. Zero atomics in the hot path. 4x unrolled
// edge loop for memory-level parallelism against L2 latency.
// =============================================================================
__device__ __forceinline__ float edge_p(float esrc, float edst) {
    float v = esrc + edst;
    v = fmaxf(v, 0.2f * v);          // leaky_relu
    return __expf(v);                // softmax shift-invariant; logits O(1)
}

__global__ void __launch_bounds__(256) gat_layer(
    const float* __restrict__ gat_b, const float* __restrict__ ln_g,
    const float* __restrict__ ln_b, const int* __restrict__ batch, int layer)
{
    int w = (blockIdx.x * blockDim.x + threadIdx.x) >> 5;
    int lane = threadIdx.x & 31;
    if (w >= N_NODES) return;

    float ed = __ldg(g_edst + w);

    // self loop
    float p = edge_p(__ldg(g_esrc + w), ed);
    float z = p;
    float4 hv = *(const float4*)(g_hfeat + (long)w * 128 + lane * 4);
    float4 acc = make_float4(p * hv.x, p * hv.y, p * hv.z, p * hv.w);

    int i   = __ldg(g_rowstart + w);
    int end = __ldg(g_rowstart + w + 1);

    for (; i + 4 <= end; i += 4) {
        int s0 = __ldg(g_csr_src + i);
        int s1 = __ldg(g_csr_src + i + 1);
        int s2 = __ldg(g_csr_src + i + 2);
        int s3 = __ldg(g_csr_src + i + 3);
        float p0 = edge_p(__ldg(g_esrc + s0), ed);
        float p1 = edge_p(__ldg(g_esrc + s1), ed);
        float p2 = edge_p(__ldg(g_esrc + s2), ed);
        float p3 = edge_p(__ldg(g_esrc + s3), ed);
        float4 h0 = *(const float4*)(g_hfeat + (long)s0 * 128 + lane * 4);
        float4 h1 = *(const float4*)(g_hfeat + (long)s1 * 128 + lane * 4);
        float4 h2 = *(const float4*)(g_hfeat + (long)s2 * 128 + lane * 4);
        float4 h3 = *(const float4*)(g_hfeat + (long)s3 * 128 + lane * 4);
        z += (p0 + p1) + (p2 + p3);
        acc.x += p0 * h0.x + p1 * h1.x + p2 * h2.x + p3 * h3.x;
        acc.y += p0 * h0.y + p1 * h1.y + p2 * h2.y + p3 * h3.y;
        acc.z += p0 * h0.z + p1 * h1.z + p2 * h2.z + p3 * h3.z;
        acc.w += p0 * h0.w + p1 * h1.w + p2 * h2.w + p3 * h3.w;
    }
    for (; i < end; i++) {
        int s0 = __ldg(g_csr_src + i);
        float p0 = edge_p(__ldg(g_esrc + s0), ed);
        float4 h0 = *(const float4*)(g_hfeat + (long)s0 * 128 + lane * 4);
        z += p0;
        acc.x += p0 * h0.x; acc.y += p0 * h0.y;
        acc.z += p0 * h0.z; acc.w += p0 * h0.w;
    }

    float inv = __fdividef(1.f, z);
    float4 b4 = *(const float4*)(gat_b + lane * 4);
    float4 v;
    v.x = acc.x * inv + b4.x;
    v.y = acc.y * inv + b4.y;
    v.z = acc.z * inv + b4.z;
    v.w = acc.w * inv + b4.w;

    // layernorm over 128 features (warp reduce)
    float s  = v.x + v.y + v.z + v.w;
    float sq = v.x * v.x + v.y * v.y + v.z * v.z + v.w * v.w;
#pragma unroll
    for (int o = 16; o > 0; o >>= 1) {
        s  += __shfl_xor_sync(0xffffffff, s,  o);
        sq += __shfl_xor_sync(0xffffffff, sq, o);
    }
    float mean = s * (1.f / 128.f);
    float var  = sq * (1.f / 128.f) - mean * mean;
    float rstd = rsqrtf(var + LN_EPS);

    float4 g4 = *(const float4*)(ln_g + lane * 4);
    float4 l4 = *(const float4*)(ln_b + lane * 4);
    float y0 = (v.x - mean) * rstd * g4.x + l4.x;
    float y1 = (v.y - mean) * rstd * g4.y + l4.y;
    float y2 = (v.z - mean) * rstd * g4.z + l4.z;
    float y3 = (v.w - mean) * rstd * g4.w + l4.w;

    if (layer < 3) {   // ELU on all but last layer
        y0 = y0 > 0.f ? y0 : expm1f(y0);
        y1 = y1 > 0.f ? y1 : expm1f(y1);
        y2 = y2 > 0.f ? y2 : expm1f(y2);
        y3 = y3 > 0.f ? y3 : expm1f(y3);
    }

    const float* skp = (layer == 0) ? g_skip : g_hcur;
    float4 sk = *(const float4*)(skp + (long)w * 128 + lane * 4);
    y0 += sk.x; y1 += sk.y; y2 += sk.z; y3 += sk.w;

    *(float4*)(g_hcur + (long)w * 128 + lane * 4) = make_float4(y0, y1, y2, y3);

    if (layer == 3) {   // fused global pooling
        int g = __ldg(batch + w);
        redAddV4(g_psum + g * 128 + lane * 4, y0, y1, y2, y3);
        float* pm = g_pmax + g * 128 + lane * 4;
        atomicMaxF(pm + 0, y0);
        atomicMaxF(pm + 1, y1);
        atomicMaxF(pm + 2, y2);
        atomicMaxF(pm + 3, y3);
        if (lane == 0) atomicAdd(&g_cnt[g], 1.f);
    }
}

// ---------------- MLP head (one block per graph) ------------------------------
__global__ void __launch_bounds__(128) mlp_head(
    const float* __restrict__ W1, const float* __restrict__ b1,
    const float* __restrict__ W2, const float* __restrict__ b2,
    const float* __restrict__ W3, const float* __restrict__ b3,
    float* __restrict__ out)
{
    __shared__ float gv[256];
    __shared__ float h1[128];
    __shared__ float h2[64];
    int g = blockIdx.x, t = threadIdx.x;

    float cnt = fmaxf(g_cnt[g], 1.f);
    gv[t]       = g_psum[g * 128 + t] / cnt;  // mean half
    gv[128 + t] = g_pmax[g * 128 + t];        // max half
    __syncthreads();

    float a1 = b1[t];
#pragma unroll 8
    for (int k = 0; k < 256; k++) a1 += gv[k] * W1[k * 128 + t];
    h1[t] = fmaxf(a1, 0.f);
    __syncthreads();

    if (t < 64) {
        float a2 = b2[t];
#pragma unroll 8
        for (int k = 0; k < 128; k++) a2 += h1[k] * W2[k * 64 + t];
        h2[t] = fmaxf(a2, 0.f);
    }
    __syncthreads();

    if (t < 4) {
        float a3 = b3[t];
#pragma unroll
        for (int k = 0; k < 64; k++) a3 += h2[k] * W3[k * 4 + t];
        out[g * 4 + t] = a3;
    }
}

// ---------------- launch ------------------------------------------------------
extern "C" void kernel_launch(void* const* d_in, const int* in_sizes, int n_in,
                              void* d_out, int out_size)
{
    const float* x      = (const float*)d_in[0];
    const int*   ei     = (const int*)  d_in[1];
    const int*   batch  = (const int*)  d_in[2];
    const float* Ws     = (const float*)d_in[3];
    const float* a_src  = (const float*)d_in[4];
    const float* a_dst  = (const float*)d_in[5];
    const float* gat_b  = (const float*)d_in[6];
    const float* ln_g   = (const float*)d_in[7];
    const float* ln_b   = (const float*)d_in[8];
    const float* skip_W = (const float*)d_in[9];
    const float* skip_b = (const float*)d_in[10];
    const float* W1 = (const float*)d_in[11];
    const float* b1 = (const float*)d_in[12];
    const float* W2 = (const float*)d_in[13];
    const float* b2 = (const float*)d_in[14];
    const float* W3 = (const float*)d_in[15];
    const float* b3 = (const float*)d_in[16];

    float *hcur, *hfeat, *skip, *esrc, *edst;
    cudaGetSymbolAddress((void**)&hcur,  g_hcur);
    cudaGetSymbolAddress((void**)&hfeat, g_hfeat);
    cudaGetSymbolAddress((void**)&skip,  g_skip);
    cudaGetSymbolAddress((void**)&esrc,  g_esrc);
    cudaGetSymbolAddress((void**)&edst,  g_edst);

    const int gemm_blocks = (N_NODES + 63) / 64;
    const int node_blocks = (N_NODES * 32 + 255) / 256;   // warp per node
    const int edge_blocks = (N_EDGES + 255) / 256;
    const int nn_blocks   = (N_NODES + 255) / 256;

    // Interleaved: CSR build + layer-0 dual GEMM as launch #4 (ncu profiles #4).
    csr_zero   <<<nn_blocks, 256>>>();                              // 1
    csr_hist   <<<edge_blocks, 256>>>(ei);                          // 2
    csr_scan1  <<<SCAN_BLK, 1024>>>();                              // 3
    gemm128_dual<<<gemm_blocks, 256>>>(x, Ws, skip_W, skip_b,       // 4 (profiled)
                                       a_src, a_dst,
                                       hfeat, skip, esrc, edst, N_NODES);
    csr_scan2  <<<1, 64>>>();                                       // 5
    csr_scan3  <<<nn_blocks, 256>>>();                              // 6
    csr_scatter<<<edge_blocks, 256>>>(ei);                          // 7

    gat_layer<<<node_blocks, 256>>>(gat_b, ln_g, ln_b, batch, 0);   // 8

    for (int l = 1; l < 4; l++) {
        gemm128<<<gemm_blocks, 256>>>(hcur, Ws + l * 128 * 128,
                                      a_src + l * 128, a_dst + l * 128,
                                      hfeat, esrc, edst, N_NODES);
        gat_layer<<<node_blocks, 256>>>(gat_b + l * 128, ln_g + l * 128,
                                        ln_b + l * 128, batch, l);
    }

    mlp_head<<<N_GRAPHS, 128>>>(W1, b1, W2, b2, W3, b3, (float*)d_out);
}